// round 2
// baseline (speedup 1.0000x reference)
#include <cuda_runtime.h>
#include <cstdint>

typedef unsigned long long ull;

#define HH 192
#define WW 192
#define HWSZ 36864
#define CHW (64*36864)
#define BB 4

// ---------- f32x2 helpers (Blackwell dual-rate fp32) ----------
__device__ __forceinline__ ull fma2(ull a, ull b, ull c) {
    ull d;
    asm("fma.rn.f32x2 %0, %1, %2, %3;" : "=l"(d) : "l"(a), "l"(b), "l"(c));
    return d;
}
__device__ __forceinline__ ull pack2(float lo, float hi) {
    ull r; asm("mov.b64 %0, {%1, %2};" : "=l"(r) : "f"(lo), "f"(hi)); return r;
}
__device__ __forceinline__ void unpack2(ull v, float& lo, float& hi) {
    asm("mov.b64 {%0, %1}, %2;" : "=f"(lo), "=f"(hi) : "l"(v));
}

// ---------- scratch (no cudaMalloc allowed) ----------
__device__ float g_x1[BB*CHW];
__device__ float g_x2[BB*CHW];
__device__ float g_tmp[BB*CHW];
__device__ float g_off[BB*98*HWSZ];
__device__ float g_wT[600000];     // transposed deform + offset-conv weights
__device__ float g_wpk_in[64*128]; // w_in transposed [c][o]
__device__ float g_wpk_out[64*64]; // w_out transposed [c][o]

// ---------- weight transposes ----------
__global__ void k_tr_deform(const float* __restrict__ w, float* __restrict__ o, int KK) {
    int idx = blockIdx.x*256 + threadIdx.x;
    if (idx >= KK*4096) return;
    int oo = idx & 63, c = (idx >> 6) & 63, k = idx >> 12;
    o[idx] = w[(oo*64 + c)*KK + k];        // out[k][c][o]
}
__global__ void k_tr_conv(const float* __restrict__ w, float* __restrict__ o, int O, int KK) {
    int idx = blockIdx.x*256 + threadIdx.x;
    if (idx >= 64*KK*O) return;
    int oo = idx % O;
    int rem = idx / O;
    int k = rem % KK;
    int ic = rem / KK;
    o[idx] = w[(oo*64 + ic)*KK + k];       // out[ic][k][o]
}
__global__ void k_tr_lin(const float* __restrict__ w, float* __restrict__ o, int O, int C) {
    int idx = blockIdx.x*256 + threadIdx.x;
    if (idx >= O*C) return;
    int oo = idx % O, c = idx / O;
    o[idx] = w[oo*C + c];                  // out[c][o]
}

// ---------- LayerNorm(channel) + 1x1 conv to 128ch, split x1/x2 ----------
__global__ __launch_bounds__(128) void k_ln_win(
    const float* __restrict__ x, const float* __restrict__ lnw,
    const float* __restrict__ lnb, const float* __restrict__ wpk,
    const float* __restrict__ bin,
    float* __restrict__ x1, float* __restrict__ x2) {
    __shared__ ull sW[4096];      // [c][o2] o2=0..63 pairs of 128 outputs
    __shared__ float sLW[64], sLB[64], sB[128];
    int t = threadIdx.x;
    const ull* wp = (const ull*)wpk;
    #pragma unroll
    for (int i = 0; i < 32; i++) sW[t + i*128] = wp[t + i*128];
    if (t < 64) { sLW[t] = lnw[t]; sLB[t] = lnb[t]; }
    sB[t] = bin[t];
    __syncthreads();
    int pix = blockIdx.x*128 + t;
    int b = pix / HWSZ, hw = pix - b*HWSZ;
    const float* xp = x + b*CHW + hw;
    float sum = 0.f, sq = 0.f;
    for (int c = 0; c < 64; c++) {
        float v = __ldg(xp + c*HWSZ);
        sum += v; sq += v*v;
    }
    float mu  = sum * 0.015625f;
    float var = sq * 0.015625f - mu*mu;
    float inv = rsqrtf(var + 1e-5f);
    #pragma unroll 1
    for (int half = 0; half < 2; half++) {
        ull acc[32];
        #pragma unroll
        for (int j = 0; j < 32; j++) acc[j] = pack2(sB[half*64+2*j], sB[half*64+2*j+1]);
        #pragma unroll 1
        for (int c = 0; c < 64; c++) {
            float v = __ldg(xp + c*HWSZ);
            v = (v - mu)*inv*sLW[c] + sLB[c];
            ull vb = pack2(v, v);
            const ull* wr = sW + c*64 + half*32;
            #pragma unroll
            for (int j = 0; j < 32; j++) acc[j] = fma2(vb, wr[j], acc[j]);
        }
        float* op = (half ? x2 : x1) + b*CHW + hw;
        #pragma unroll
        for (int j = 0; j < 32; j++) {
            float lo, hi; unpack2(acc[j], lo, hi);
            op[(2*j)*HWSZ] = lo; op[(2*j+1)*HWSZ] = hi;
        }
    }
}

// ---------- direct conv (offset branches): 32x32 tile, 2x2 px/thread, 16 oc ----------
template<int K, int OTOT>
__global__ __launch_bounds__(256) void k_conv(
    const float* __restrict__ src, const float* __restrict__ owT,
    const float* __restrict__ bias, float* __restrict__ dst) {
    constexpr int PAD = K/2;
    constexpr int KK  = K*K;
    constexpr int TIW = 32 + K - 1;
    constexpr int OG  = (OTOT + 15)/16;
    __shared__ float sIn[4*TIW*TIW];
    __shared__ ull   sW[4*KK*8];
    int t  = threadIdx.x;
    int tx = t & 15, ty = t >> 4;
    int bz = blockIdx.z;
    int og = bz % OG;
    int b  = bz / OG;
    int oc0 = og*16;
    int ox0 = blockIdx.x*32, oy0 = blockIdx.y*32;
    int gx0 = ox0 - PAD, gy0 = oy0 - PAD;
    const float* sb = src + b*CHW;
    ull acc[2][2][8];
    #pragma unroll
    for (int dy = 0; dy < 2; dy++)
    #pragma unroll
    for (int dx = 0; dx < 2; dx++)
    #pragma unroll
    for (int j = 0; j < 8; j++) acc[dy][dx][j] = 0ULL;

    #pragma unroll 1
    for (int ic0 = 0; ic0 < 64; ic0 += 4) {
        __syncthreads();
        for (int i = t; i < 4*TIW*TIW; i += 256) {
            int ic = i / (TIW*TIW);
            int r  = i - ic*TIW*TIW;
            int yy = r / TIW, xx = r - yy*TIW;
            int gy = gy0 + yy, gx = gx0 + xx;
            float v = 0.f;
            if (gy >= 0 && gy < HH && gx >= 0 && gx < WW)
                v = __ldg(sb + (ic0+ic)*HWSZ + gy*WW + gx);
            sIn[i] = v;
        }
        for (int i = t; i < 4*KK*8; i += 256) {
            int j  = i & 7;
            int rem = i >> 3;
            int k  = rem % KK;
            int ic = rem / KK;
            int oc = oc0 + 2*j;
            ull v = 0ULL;
            if (oc < OTOT)
                v = *(const ull*)(owT + (size_t)((ic0+ic)*KK + k)*OTOT + oc);
            sW[i] = v;
        }
        __syncthreads();
        #pragma unroll 1
        for (int ic = 0; ic < 4; ic++) {
            #pragma unroll 1
            for (int ky = 0; ky < K; ky++) {
                #pragma unroll
                for (int kx = 0; kx < K; kx++) {
                    ull v2[2][2];
                    #pragma unroll
                    for (int dy = 0; dy < 2; dy++)
                    #pragma unroll
                    for (int dx = 0; dx < 2; dx++) {
                        float f = sIn[ic*TIW*TIW + (2*ty+ky+dy)*TIW + 2*tx+kx+dx];
                        v2[dy][dx] = pack2(f, f);
                    }
                    const ull* wr = sW + (ic*KK + ky*K + kx)*8;
                    #pragma unroll
                    for (int j = 0; j < 8; j++) {
                        ull wv = wr[j];
                        acc[0][0][j] = fma2(v2[0][0], wv, acc[0][0][j]);
                        acc[0][1][j] = fma2(v2[0][1], wv, acc[0][1][j]);
                        acc[1][0][j] = fma2(v2[1][0], wv, acc[1][0][j]);
                        acc[1][1][j] = fma2(v2[1][1], wv, acc[1][1][j]);
                    }
                }
            }
        }
    }
    #pragma unroll
    for (int j = 0; j < 8; j++) {
        int oc = oc0 + 2*j;
        if (oc < OTOT) {
            float b0 = __ldg(bias + oc), b1 = __ldg(bias + oc + 1);
            #pragma unroll
            for (int dy = 0; dy < 2; dy++)
            #pragma unroll
            for (int dx = 0; dx < 2; dx++) {
                float lo, hi; unpack2(acc[dy][dx][j], lo, hi);
                int py = oy0 + 2*ty + dy, px = ox0 + 2*tx + dx;
                float* dp = dst + (size_t)b*OTOT*HWSZ + oc*HWSZ + py*WW + px;
                dp[0]    = lo + b0;
                dp[HWSZ] = hi + b1;
            }
        }
    }
}

// ---------- deformable conv: 2 rows x 64 cols per block, 2 px/thread ----------
template<int K, int PAD>
__global__ __launch_bounds__(64) void k_deform(
    const float* __restrict__ src, const float* __restrict__ off,
    const float* __restrict__ wT, const float* __restrict__ bias,
    float* __restrict__ dst) {
    constexpr int KK = K*K;
    __shared__ ull sW[2048];      // [c][o2] for current tap
    int t = threadIdx.x;
    int xcol = blockIdx.x*64 + t;
    int h0 = blockIdx.y*2;
    int b = blockIdx.z;
    const float* srcb = src + b*CHW;
    const float* offb = off + (size_t)b*(2*KK)*HWSZ;
    ull acc[2][32];
    #pragma unroll
    for (int p = 0; p < 2; p++)
    #pragma unroll
    for (int j = 0; j < 32; j++) acc[p][j] = 0ULL;

    #pragma unroll 1
    for (int k = 0; k < KK; k++) {
        __syncthreads();
        const ull* wk = (const ull*)(wT + k*4096);
        #pragma unroll
        for (int i = 0; i < 32; i++) sW[t + i*64] = wk[t + i*64];
        __syncthreads();
        int ki = k / K, kj = k - ki*K;
        float cw[2][4];
        int   ofs[2][4];
        #pragma unroll
        for (int p = 0; p < 2; p++) {
            int hh = h0 + p;
            int pixi = hh*WW + xcol;
            float oy = __ldg(offb + (size_t)(2*k)*HWSZ + pixi);
            float ox = __ldg(offb + (size_t)(2*k+1)*HWSZ + pixi);
            float py = (float)(hh + ki - PAD) + oy;
            float px = (float)(xcol + kj - PAD) + ox;
            float y0f = floorf(py), x0f = floorf(px);
            float wy = py - y0f, wx = px - x0f;
            int y0 = (int)y0f, x0 = (int)x0f;
            int y1 = y0 + 1, x1i = x0 + 1;
            float my0 = (y0  >= 0 && y0  < HH) ? 1.f : 0.f;
            float my1 = (y1  >= 0 && y1  < HH) ? 1.f : 0.f;
            float mx0 = (x0  >= 0 && x0  < WW) ? 1.f : 0.f;
            float mx1 = (x1i >= 0 && x1i < WW) ? 1.f : 0.f;
            int yc0 = min(max(y0, 0), HH-1), yc1 = min(max(y1, 0), HH-1);
            int xc0 = min(max(x0, 0), WW-1), xc1 = min(max(x1i, 0), WW-1);
            cw[p][0] = my0*mx0*(1.f-wy)*(1.f-wx);
            cw[p][1] = my0*mx1*(1.f-wy)*wx;
            cw[p][2] = my1*mx0*wy*(1.f-wx);
            cw[p][3] = my1*mx1*wy*wx;
            ofs[p][0] = yc0*WW + xc0;
            ofs[p][1] = yc0*WW + xc1;
            ofs[p][2] = yc1*WW + xc0;
            ofs[p][3] = yc1*WW + xc1;
        }
        #pragma unroll 2
        for (int c = 0; c < 64; c++) {
            const float* sp = srcb + c*HWSZ;
            float s0 = __ldg(sp+ofs[0][0])*cw[0][0] + __ldg(sp+ofs[0][1])*cw[0][1]
                     + __ldg(sp+ofs[0][2])*cw[0][2] + __ldg(sp+ofs[0][3])*cw[0][3];
            float s1 = __ldg(sp+ofs[1][0])*cw[1][0] + __ldg(sp+ofs[1][1])*cw[1][1]
                     + __ldg(sp+ofs[1][2])*cw[1][2] + __ldg(sp+ofs[1][3])*cw[1][3];
            ull s0b = pack2(s0, s0), s1b = pack2(s1, s1);
            const ull* wc = sW + c*32;
            #pragma unroll
            for (int j = 0; j < 32; j++) {
                acc[0][j] = fma2(s0b, wc[j], acc[0][j]);
                acc[1][j] = fma2(s1b, wc[j], acc[1][j]);
            }
        }
    }
    #pragma unroll
    for (int p = 0; p < 2; p++) {
        float* dp = dst + b*CHW + (h0+p)*WW + xcol;
        #pragma unroll
        for (int j = 0; j < 32; j++) {
            float lo, hi; unpack2(acc[p][j], lo, hi);
            dp[(2*j)*HWSZ]   = lo + __ldg(bias + 2*j);
            dp[(2*j+1)*HWSZ] = hi + __ldg(bias + 2*j + 1);
        }
    }
}

// ---------- final: (x1+x2) @ w_out + b_out + residual ----------
__global__ __launch_bounds__(128) void k_final(
    const float* __restrict__ t1, const float* __restrict__ t2,
    const float* __restrict__ xres, const float* __restrict__ wpk,
    const float* __restrict__ bout, float* __restrict__ out) {
    __shared__ ull sW[2048];
    __shared__ float sB[64];
    int t = threadIdx.x;
    const ull* wp = (const ull*)wpk;
    #pragma unroll
    for (int i = 0; i < 16; i++) sW[t + i*128] = wp[t + i*128];
    if (t < 64) sB[t] = bout[t];
    __syncthreads();
    int pix = blockIdx.x*128 + t;
    int b = pix / HWSZ, hw = pix - b*HWSZ;
    const float* p1 = t1 + b*CHW + hw;
    const float* p2 = t2 + b*CHW + hw;
    ull acc[32];
    #pragma unroll
    for (int j = 0; j < 32; j++) acc[j] = pack2(sB[2*j], sB[2*j+1]);
    #pragma unroll 1
    for (int c = 0; c < 64; c++) {
        float v = __ldg(p1 + c*HWSZ) + __ldg(p2 + c*HWSZ);
        ull vb = pack2(v, v);
        const ull* wc = sW + c*32;
        #pragma unroll
        for (int j = 0; j < 32; j++) acc[j] = fma2(vb, wc[j], acc[j]);
    }
    const float* xr = xres + b*CHW + hw;
    float* op = out + b*CHW + hw;
    #pragma unroll
    for (int j = 0; j < 32; j++) {
        float lo, hi; unpack2(acc[j], lo, hi);
        op[(2*j)*HWSZ]   = lo + __ldg(xr + (2*j)*HWSZ);
        op[(2*j+1)*HWSZ] = hi + __ldg(xr + (2*j+1)*HWSZ);
    }
}

extern "C" void kernel_launch(void* const* d_in, const int* in_sizes, int n_in,
                              void* d_out, int out_size) {
    const float* x    = (const float*)d_in[0];
    const float* lnw  = (const float*)d_in[1];
    const float* lnb  = (const float*)d_in[2];
    const float* w_in = (const float*)d_in[3];
    const float* b_in = (const float*)d_in[4];
    const float* w_out= (const float*)d_in[5];
    const float* b_out= (const float*)d_in[6];
    const float* dw1  = (const float*)d_in[7];
    const float* db1  = (const float*)d_in[8];
    const float* dw2  = (const float*)d_in[9];
    const float* db2  = (const float*)d_in[10];
    const float* dw3  = (const float*)d_in[11];
    const float* db3  = (const float*)d_in[12];
    const float* ow1  = (const float*)d_in[13];
    const float* ob1  = (const float*)d_in[14];
    const float* ow2  = (const float*)d_in[15];
    const float* ob2  = (const float*)d_in[16];
    const float* ow3  = (const float*)d_in[17];
    const float* ob3  = (const float*)d_in[18];
    float* out = (float*)d_out;

    float *x1, *x2, *tmp, *offb, *wT, *wpi, *wpo;
    cudaGetSymbolAddress((void**)&x1,  g_x1);
    cudaGetSymbolAddress((void**)&x2,  g_x2);
    cudaGetSymbolAddress((void**)&tmp, g_tmp);
    cudaGetSymbolAddress((void**)&offb,g_off);
    cudaGetSymbolAddress((void**)&wT,  g_wT);
    cudaGetSymbolAddress((void**)&wpi, g_wpk_in);
    cudaGetSymbolAddress((void**)&wpo, g_wpk_out);

    const int WD1 = 0, WD2 = 49*4096, WD3 = 74*4096;
    const int WO1 = 83*4096;
    const int WO2 = WO1 + 64*25*98;
    const int WO3 = WO2 + 64*25*50;

    k_tr_deform<<<(49*4096+255)/256, 256>>>(dw1, wT+WD1, 49);
    k_tr_deform<<<(25*4096+255)/256, 256>>>(dw2, wT+WD2, 25);
    k_tr_deform<<<( 9*4096+255)/256, 256>>>(dw3, wT+WD3, 9);
    k_tr_conv<<<(64*25*98+255)/256, 256>>>(ow1, wT+WO1, 98, 25);
    k_tr_conv<<<(64*25*50+255)/256, 256>>>(ow2, wT+WO2, 50, 25);
    k_tr_conv<<<(64*9*18+255)/256, 256>>>(ow3, wT+WO3, 18, 9);
    k_tr_lin<<<(64*128+255)/256, 256>>>(w_in,  wpi, 128, 64);
    k_tr_lin<<<(64*64+255)/256, 256>>>(w_out, wpo, 64, 64);

    k_ln_win<<<BB*HWSZ/128, 128>>>(x, lnw, lnb, wpi, b_in, x1, x2);

    k_conv<5,98><<<dim3(6,6,4*7), 256>>>(x1,  wT+WO1, ob1, offb);
    k_deform<7,3><<<dim3(3,96,4), 64>>>(x1,  offb, wT+WD1, db1, tmp);
    k_conv<5,50><<<dim3(6,6,4*4), 256>>>(tmp, wT+WO2, ob2, offb);
    k_deform<5,2><<<dim3(3,96,4), 64>>>(tmp, offb, wT+WD2, db2, x1);
    k_conv<3,18><<<dim3(6,6,4*2), 256>>>(x1,  wT+WO3, ob3, offb);
    k_deform<3,1><<<dim3(3,96,4), 64>>>(x1,  offb, wT+WD3, db3, tmp);

    k_final<<<BB*HWSZ/128, 128>>>(tmp, x2, x, wpo, b_out, out);
}

// round 3
// speedup vs baseline: 1.6302x; 1.6302x over previous
#include <cuda_runtime.h>
#include <cstdint>

typedef unsigned long long ull;

#define HH 192
#define WW 192
#define HWSZ 36864
#define CHW (64*36864)
#define BB 4

// ---------- f32x2 helpers (Blackwell dual-rate fp32) ----------
__device__ __forceinline__ ull fma2(ull a, ull b, ull c) {
    ull d;
    asm("fma.rn.f32x2 %0, %1, %2, %3;" : "=l"(d) : "l"(a), "l"(b), "l"(c));
    return d;
}
__device__ __forceinline__ ull pack2(float lo, float hi) {
    ull r; asm("mov.b64 %0, {%1, %2};" : "=l"(r) : "f"(lo), "f"(hi)); return r;
}
__device__ __forceinline__ void unpack2(ull v, float& lo, float& hi) {
    asm("mov.b64 {%0, %1}, %2;" : "=f"(lo), "=f"(hi) : "l"(v));
}

// ---------- scratch (no cudaMalloc allowed) ----------
__device__ __align__(16) float g_x1[BB*CHW];
__device__ __align__(16) float g_x2[BB*CHW];
__device__ __align__(16) float g_tmp[BB*CHW];
__device__ __align__(16) float g_off[BB*98*HWSZ];
__device__ __align__(16) float g_wT[600000];     // transposed deform + offset-conv weights
__device__ __align__(16) float g_wpk_in[64*128]; // w_in transposed [c][o]
__device__ __align__(16) float g_wpk_out[64*64]; // w_out transposed [c][o]

// ---------- weight transposes ----------
__global__ void k_tr_deform(const float* __restrict__ w, float* __restrict__ o, int KK) {
    int idx = blockIdx.x*256 + threadIdx.x;
    if (idx >= KK*4096) return;
    int oo = idx & 63, c = (idx >> 6) & 63, k = idx >> 12;
    o[idx] = w[(oo*64 + c)*KK + k];        // out[k][c][o]
}
__global__ void k_tr_conv(const float* __restrict__ w, float* __restrict__ o, int O, int KK) {
    int idx = blockIdx.x*256 + threadIdx.x;
    if (idx >= 64*KK*O) return;
    int oo = idx % O;
    int rem = idx / O;
    int k = rem % KK;
    int ic = rem / KK;
    o[idx] = w[(oo*64 + ic)*KK + k];       // out[ic][k][o]
}
__global__ void k_tr_lin(const float* __restrict__ w, float* __restrict__ o, int O, int C) {
    int idx = blockIdx.x*256 + threadIdx.x;
    if (idx >= O*C) return;
    int oo = idx % O, c = idx / O;
    o[idx] = w[oo*C + c];                  // out[c][o]
}

// ---------- LayerNorm(channel) + 1x1 conv to 128ch, split x1/x2 ----------
__global__ __launch_bounds__(128) void k_ln_win(
    const float* __restrict__ x, const float* __restrict__ lnw,
    const float* __restrict__ lnb, const float* __restrict__ wpk,
    const float* __restrict__ bin,
    float* __restrict__ x1, float* __restrict__ x2) {
    __shared__ ull sW[4096];      // [c][o2] o2=0..63 pairs of 128 outputs
    __shared__ float sLW[64], sLB[64], sB[128];
    int t = threadIdx.x;
    const ull* wp = (const ull*)wpk;
    #pragma unroll
    for (int i = 0; i < 32; i++) sW[t + i*128] = wp[t + i*128];
    if (t < 64) { sLW[t] = lnw[t]; sLB[t] = lnb[t]; }
    sB[t] = bin[t];
    __syncthreads();
    int pix = blockIdx.x*128 + t;
    int b = pix / HWSZ, hw = pix - b*HWSZ;
    const float* xp = x + b*CHW + hw;
    float sum = 0.f, sq = 0.f;
    for (int c = 0; c < 64; c++) {
        float v = __ldg(xp + c*HWSZ);
        sum += v; sq += v*v;
    }
    float mu  = sum * 0.015625f;
    float var = sq * 0.015625f - mu*mu;
    float inv = rsqrtf(var + 1e-5f);
    #pragma unroll 1
    for (int half = 0; half < 2; half++) {
        ull acc[32];
        #pragma unroll
        for (int j = 0; j < 32; j++) acc[j] = pack2(sB[half*64+2*j], sB[half*64+2*j+1]);
        #pragma unroll 1
        for (int c = 0; c < 64; c++) {
            float v = __ldg(xp + c*HWSZ);
            v = (v - mu)*inv*sLW[c] + sLB[c];
            ull vb = pack2(v, v);
            const ull* wr = sW + c*64 + half*32;
            #pragma unroll
            for (int j = 0; j < 32; j++) acc[j] = fma2(vb, wr[j], acc[j]);
        }
        float* op = (half ? x2 : x1) + b*CHW + hw;
        #pragma unroll
        for (int j = 0; j < 32; j++) {
            float lo, hi; unpack2(acc[j], lo, hi);
            op[(2*j)*HWSZ] = lo; op[(2*j+1)*HWSZ] = hi;
        }
    }
}

// ---------- direct conv (offset branches): 32x32 tile, 2x2 px/thread, 16 oc ----------
template<int K, int OTOT>
__global__ __launch_bounds__(256) void k_conv(
    const float* __restrict__ src, const float* __restrict__ owT,
    const float* __restrict__ bias, float* __restrict__ dst) {
    constexpr int PAD = K/2;
    constexpr int KK  = K*K;
    constexpr int TIW = 32 + K - 1;
    constexpr int OG  = (OTOT + 15)/16;
    __shared__ float sIn[4*TIW*TIW];
    __shared__ ull   sW[4*KK*8];
    int t  = threadIdx.x;
    int tx = t & 15, ty = t >> 4;
    int bz = blockIdx.z;
    int og = bz % OG;
    int b  = bz / OG;
    int oc0 = og*16;
    int ox0 = blockIdx.x*32, oy0 = blockIdx.y*32;
    int gx0 = ox0 - PAD, gy0 = oy0 - PAD;
    const float* sb = src + b*CHW;
    ull acc[2][2][8];
    #pragma unroll
    for (int dy = 0; dy < 2; dy++)
    #pragma unroll
    for (int dx = 0; dx < 2; dx++)
    #pragma unroll
    for (int j = 0; j < 8; j++) acc[dy][dx][j] = 0ULL;

    #pragma unroll 1
    for (int ic0 = 0; ic0 < 64; ic0 += 4) {
        __syncthreads();
        for (int i = t; i < 4*TIW*TIW; i += 256) {
            int ic = i / (TIW*TIW);
            int r  = i - ic*TIW*TIW;
            int yy = r / TIW, xx = r - yy*TIW;
            int gy = gy0 + yy, gx = gx0 + xx;
            float v = 0.f;
            if (gy >= 0 && gy < HH && gx >= 0 && gx < WW)
                v = __ldg(sb + (ic0+ic)*HWSZ + gy*WW + gx);
            sIn[i] = v;
        }
        for (int i = t; i < 4*KK*8; i += 256) {
            int j  = i & 7;
            int rem = i >> 3;
            int k  = rem % KK;
            int ic = rem / KK;
            int oc = oc0 + 2*j;
            ull v = 0ULL;
            if (oc < OTOT)
                v = *(const ull*)(owT + (size_t)((ic0+ic)*KK + k)*OTOT + oc);
            sW[i] = v;
        }
        __syncthreads();
        #pragma unroll 1
        for (int ic = 0; ic < 4; ic++) {
            #pragma unroll 1
            for (int ky = 0; ky < K; ky++) {
                #pragma unroll
                for (int kx = 0; kx < K; kx++) {
                    ull v2[2][2];
                    #pragma unroll
                    for (int dy = 0; dy < 2; dy++)
                    #pragma unroll
                    for (int dx = 0; dx < 2; dx++) {
                        float f = sIn[ic*TIW*TIW + (2*ty+ky+dy)*TIW + 2*tx+kx+dx];
                        v2[dy][dx] = pack2(f, f);
                    }
                    const ull* wr = sW + (ic*KK + ky*K + kx)*8;
                    #pragma unroll
                    for (int j = 0; j < 8; j++) {
                        ull wv = wr[j];
                        acc[0][0][j] = fma2(v2[0][0], wv, acc[0][0][j]);
                        acc[0][1][j] = fma2(v2[0][1], wv, acc[0][1][j]);
                        acc[1][0][j] = fma2(v2[1][0], wv, acc[1][0][j]);
                        acc[1][1][j] = fma2(v2[1][1], wv, acc[1][1][j]);
                    }
                }
            }
        }
    }
    #pragma unroll
    for (int j = 0; j < 8; j++) {
        int oc = oc0 + 2*j;
        if (oc < OTOT) {
            float b0 = __ldg(bias + oc), b1 = __ldg(bias + oc + 1);
            #pragma unroll
            for (int dy = 0; dy < 2; dy++)
            #pragma unroll
            for (int dx = 0; dx < 2; dx++) {
                float lo, hi; unpack2(acc[dy][dx][j], lo, hi);
                int py = oy0 + 2*ty + dy, px = ox0 + 2*tx + dx;
                float* dp = dst + (size_t)b*OTOT*HWSZ + oc*HWSZ + py*WW + px;
                dp[0]    = lo + b0;
                dp[HWSZ] = hi + b1;
            }
        }
    }
}

// ---------- deformable conv v2: sample-stage + register-tiled GEMM ----------
// Block: 256 threads, tile = 128 linear pixels x 64 oc, K-loop over 64 channels per tap.
// smem: duplicated weights (f32x2) 32KB + samples 32KB + coords 4KB = 69632B.
// Thread map: px_t = t&31 (4 px each), oc_t = t>>5 (8 oc each) -> warp-uniform oc
// => weight LDS are broadcasts, sample LDS.128 fully coalesced.
template<int K, int PAD>
__global__ __launch_bounds__(256) void k_deform2(
    const float* __restrict__ src, const float* __restrict__ off,
    const float* __restrict__ wT, const float* __restrict__ bias,
    float* __restrict__ dst) {
    constexpr int KK = K*K;
    extern __shared__ char smem[];
    ull*   sWd = (ull*)smem;                  // [c][64 oc] duplicated f32x2, 32768B
    float* sS  = (float*)(smem + 32768);      // [c][128 px], 32768B
    float* sCW = (float*)(smem + 65536);      // [4][128]
    int*   sOF = (int*)  (smem + 67584);      // [4][128]

    int t = threadIdx.x;
    int hw0 = blockIdx.x * 128;
    int b   = blockIdx.y;
    const float* srcb = src + b*CHW;
    const float* offb = off + (size_t)b*(2*KK)*HWSZ;

    int px_t = t & 31;        // pixel group (4 px)
    int oc_t = t >> 5;        // oc group (8 oc) -- uniform per warp
    int spx  = t & 127;       // sampling pixel
    int c0   = (t >> 7) * 32; // sampling channel base

    ull acc[2][8];
    #pragma unroll
    for (int pp = 0; pp < 2; pp++)
    #pragma unroll
    for (int j = 0; j < 8; j++) acc[pp][j] = 0ULL;

    #pragma unroll 1
    for (int k = 0; k < KK; k++) {
        __syncthreads();
        // --- stage coords (threads 0..127, one pixel each) ---
        if (t < 128) {
            int hw = hw0 + t;
            int hh = hw / WW, xx = hw - hh*WW;
            float oy = __ldg(offb + (size_t)(2*k)*HWSZ + hw);
            float ox = __ldg(offb + (size_t)(2*k+1)*HWSZ + hw);
            int ki = k / K, kj = k - ki*K;
            float py = (float)(hh + ki - PAD) + oy;
            float px = (float)(xx + kj - PAD) + ox;
            float y0f = floorf(py), x0f = floorf(px);
            float wy = py - y0f, wx = px - x0f;
            int y0 = (int)y0f, x0 = (int)x0f;
            int y1 = y0 + 1, x1i = x0 + 1;
            float my0 = (y0  >= 0 && y0  < HH) ? 1.f : 0.f;
            float my1 = (y1  >= 0 && y1  < HH) ? 1.f : 0.f;
            float mx0 = (x0  >= 0 && x0  < WW) ? 1.f : 0.f;
            float mx1 = (x1i >= 0 && x1i < WW) ? 1.f : 0.f;
            int yc0 = min(max(y0, 0), HH-1), yc1 = min(max(y1, 0), HH-1);
            int xc0 = min(max(x0, 0), WW-1), xc1 = min(max(x1i, 0), WW-1);
            sCW[0*128+t] = my0*mx0*(1.f-wy)*(1.f-wx);
            sCW[1*128+t] = my0*mx1*(1.f-wy)*wx;
            sCW[2*128+t] = my1*mx0*wy*(1.f-wx);
            sCW[3*128+t] = my1*mx1*wy*wx;
            sOF[0*128+t] = yc0*WW + xc0;
            sOF[1*128+t] = yc0*WW + xc1;
            sOF[2*128+t] = yc1*WW + xc0;
            sOF[3*128+t] = yc1*WW + xc1;
        }
        // --- stage weights (duplicated to f32x2) ---
        {
            const float4* wk = (const float4*)(wT + k*4096);
            #pragma unroll
            for (int i = 0; i < 4; i++) {
                int idx = t + i*256;
                float4 v = __ldg(wk + idx);
                ull* wd = sWd + idx*4;
                wd[0] = pack2(v.x, v.x);
                wd[1] = pack2(v.y, v.y);
                wd[2] = pack2(v.z, v.z);
                wd[3] = pack2(v.w, v.w);
            }
        }
        __syncthreads();
        // --- sampling: 32 channels per thread for pixel spx ---
        {
            float w0 = sCW[spx],       w1 = sCW[128+spx];
            float w2 = sCW[256+spx],   w3 = sCW[384+spx];
            int   o0 = sOF[spx],       o1 = sOF[128+spx];
            int   o2 = sOF[256+spx],   o3 = sOF[384+spx];
            const float* sp0 = srcb + c0*HWSZ;
            #pragma unroll 4
            for (int i = 0; i < 32; i++) {
                const float* p = sp0 + i*HWSZ;
                float v = __ldg(p+o0)*w0 + __ldg(p+o1)*w1
                        + __ldg(p+o2)*w2 + __ldg(p+o3)*w3;
                sS[(c0+i)*128 + spx] = v;
            }
        }
        __syncthreads();
        // --- GEMM: 64 c iters, 5 LDS.128 + 16 fma2 each ---
        {
            const float* sSp = sS + px_t*4;
            const ulonglong2* wp2 = (const ulonglong2*)(sWd + oc_t*8);
            #pragma unroll 4
            for (int c = 0; c < 64; c++) {
                ulonglong2 sv = *(const ulonglong2*)(sSp + c*128);
                ulonglong2 w01 = wp2[c*32 + 0];
                ulonglong2 w23 = wp2[c*32 + 1];
                ulonglong2 w45 = wp2[c*32 + 2];
                ulonglong2 w67 = wp2[c*32 + 3];
                acc[0][0] = fma2(sv.x, w01.x, acc[0][0]);
                acc[1][0] = fma2(sv.y, w01.x, acc[1][0]);
                acc[0][1] = fma2(sv.x, w01.y, acc[0][1]);
                acc[1][1] = fma2(sv.y, w01.y, acc[1][1]);
                acc[0][2] = fma2(sv.x, w23.x, acc[0][2]);
                acc[1][2] = fma2(sv.y, w23.x, acc[1][2]);
                acc[0][3] = fma2(sv.x, w23.y, acc[0][3]);
                acc[1][3] = fma2(sv.y, w23.y, acc[1][3]);
                acc[0][4] = fma2(sv.x, w45.x, acc[0][4]);
                acc[1][4] = fma2(sv.y, w45.x, acc[1][4]);
                acc[0][5] = fma2(sv.x, w45.y, acc[0][5]);
                acc[1][5] = fma2(sv.y, w45.y, acc[1][5]);
                acc[0][6] = fma2(sv.x, w67.x, acc[0][6]);
                acc[1][6] = fma2(sv.y, w67.x, acc[1][6]);
                acc[0][7] = fma2(sv.x, w67.y, acc[0][7]);
                acc[1][7] = fma2(sv.y, w67.y, acc[1][7]);
            }
        }
    }
    // --- epilogue: bias + store (each ull = {px even, px odd} for one oc) ---
    float* db = dst + b*CHW;
    #pragma unroll
    for (int pp = 0; pp < 2; pp++) {
        int hw = hw0 + px_t*4 + pp*2;
        #pragma unroll
        for (int j = 0; j < 8; j++) {
            int oc = oc_t*8 + j;
            float lo, hi; unpack2(acc[pp][j], lo, hi);
            float bb = __ldg(bias + oc);
            *(float2*)(db + (size_t)oc*HWSZ + hw) = make_float2(lo + bb, hi + bb);
        }
    }
}

// ---------- final: (x1+x2) @ w_out + b_out + residual ----------
__global__ __launch_bounds__(128) void k_final(
    const float* __restrict__ t1, const float* __restrict__ t2,
    const float* __restrict__ xres, const float* __restrict__ wpk,
    const float* __restrict__ bout, float* __restrict__ out) {
    __shared__ ull sW[2048];
    __shared__ float sB[64];
    int t = threadIdx.x;
    const ull* wp = (const ull*)wpk;
    #pragma unroll
    for (int i = 0; i < 16; i++) sW[t + i*128] = wp[t + i*128];
    if (t < 64) sB[t] = bout[t];
    __syncthreads();
    int pix = blockIdx.x*128 + t;
    int b = pix / HWSZ, hw = pix - b*HWSZ;
    const float* p1 = t1 + b*CHW + hw;
    const float* p2 = t2 + b*CHW + hw;
    ull acc[32];
    #pragma unroll
    for (int j = 0; j < 32; j++) acc[j] = pack2(sB[2*j], sB[2*j+1]);
    #pragma unroll 1
    for (int c = 0; c < 64; c++) {
        float v = __ldg(p1 + c*HWSZ) + __ldg(p2 + c*HWSZ);
        ull vb = pack2(v, v);
        const ull* wc = sW + c*32;
        #pragma unroll
        for (int j = 0; j < 32; j++) acc[j] = fma2(vb, wc[j], acc[j]);
    }
    const float* xr = xres + b*CHW + hw;
    float* op = out + b*CHW + hw;
    #pragma unroll
    for (int j = 0; j < 32; j++) {
        float lo, hi; unpack2(acc[j], lo, hi);
        op[(2*j)*HWSZ]   = lo + __ldg(xr + (2*j)*HWSZ);
        op[(2*j+1)*HWSZ] = hi + __ldg(xr + (2*j+1)*HWSZ);
    }
}

extern "C" void kernel_launch(void* const* d_in, const int* in_sizes, int n_in,
                              void* d_out, int out_size) {
    const float* x    = (const float*)d_in[0];
    const float* lnw  = (const float*)d_in[1];
    const float* lnb  = (const float*)d_in[2];
    const float* w_in = (const float*)d_in[3];
    const float* b_in = (const float*)d_in[4];
    const float* w_out= (const float*)d_in[5];
    const float* b_out= (const float*)d_in[6];
    const float* dw1  = (const float*)d_in[7];
    const float* db1  = (const float*)d_in[8];
    const float* dw2  = (const float*)d_in[9];
    const float* db2  = (const float*)d_in[10];
    const float* dw3  = (const float*)d_in[11];
    const float* db3  = (const float*)d_in[12];
    const float* ow1  = (const float*)d_in[13];
    const float* ob1  = (const float*)d_in[14];
    const float* ow2  = (const float*)d_in[15];
    const float* ob2  = (const float*)d_in[16];
    const float* ow3  = (const float*)d_in[17];
    const float* ob3  = (const float*)d_in[18];
    float* out = (float*)d_out;

    float *x1, *x2, *tmp, *offb, *wT, *wpi, *wpo;
    cudaGetSymbolAddress((void**)&x1,  g_x1);
    cudaGetSymbolAddress((void**)&x2,  g_x2);
    cudaGetSymbolAddress((void**)&tmp, g_tmp);
    cudaGetSymbolAddress((void**)&offb,g_off);
    cudaGetSymbolAddress((void**)&wT,  g_wT);
    cudaGetSymbolAddress((void**)&wpi, g_wpk_in);
    cudaGetSymbolAddress((void**)&wpo, g_wpk_out);

    const int SMEM_DEF = 69632;
    cudaFuncSetAttribute(k_deform2<7,3>, cudaFuncAttributeMaxDynamicSharedMemorySize, SMEM_DEF);
    cudaFuncSetAttribute(k_deform2<5,2>, cudaFuncAttributeMaxDynamicSharedMemorySize, SMEM_DEF);
    cudaFuncSetAttribute(k_deform2<3,1>, cudaFuncAttributeMaxDynamicSharedMemorySize, SMEM_DEF);

    const int WD1 = 0, WD2 = 49*4096, WD3 = 74*4096;
    const int WO1 = 83*4096;
    const int WO2 = WO1 + 64*25*98;
    const int WO3 = WO2 + 64*25*50;

    k_tr_deform<<<(49*4096+255)/256, 256>>>(dw1, wT+WD1, 49);
    k_tr_deform<<<(25*4096+255)/256, 256>>>(dw2, wT+WD2, 25);
    k_tr_deform<<<( 9*4096+255)/256, 256>>>(dw3, wT+WD3, 9);
    k_tr_conv<<<(64*25*98+255)/256, 256>>>(ow1, wT+WO1, 98, 25);
    k_tr_conv<<<(64*25*50+255)/256, 256>>>(ow2, wT+WO2, 50, 25);
    k_tr_conv<<<(64*9*18+255)/256, 256>>>(ow3, wT+WO3, 18, 9);
    k_tr_lin<<<(64*128+255)/256, 256>>>(w_in,  wpi, 128, 64);
    k_tr_lin<<<(64*64+255)/256, 256>>>(w_out, wpo, 64, 64);

    k_ln_win<<<BB*HWSZ/128, 128>>>(x, lnw, lnb, wpi, b_in, x1, x2);

    k_conv<5,98><<<dim3(6,6,4*7), 256>>>(x1,  wT+WO1, ob1, offb);
    k_deform2<7,3><<<dim3(288,4), 256, SMEM_DEF>>>(x1,  offb, wT+WD1, db1, tmp);
    k_conv<5,50><<<dim3(6,6,4*4), 256>>>(tmp, wT+WO2, ob2, offb);
    k_deform2<5,2><<<dim3(288,4), 256, SMEM_DEF>>>(tmp, offb, wT+WD2, db2, x1);
    k_conv<3,18><<<dim3(6,6,4*2), 256>>>(x1,  wT+WO3, ob3, offb);
    k_deform2<3,1><<<dim3(288,4), 256, SMEM_DEF>>>(x1,  offb, wT+WD3, db3, tmp);

    k_final<<<BB*HWSZ/128, 128>>>(tmp, x2, x, wpo, b_out, out);
}